// round 6
// baseline (speedup 1.0000x reference)
#include <cuda_runtime.h>
#include <math.h>

// Shapes (fixed by setup_inputs)
// nodes [320,256,64], global_attr [64*256,16], edges [2,1280], out [64,4] f32
// LSTMs: msg 4H=512,H=128,Din=144 ; upd 512/128/208 ; grp 256/64/144 ; act 16/4/192

__device__ float d_WihmT[144*512];
__device__ float d_WhhmT[128*512];
__device__ float d_WihuT[208*512];
__device__ float d_WhhuT[128*512];
__device__ float d_WihgT[144*256];
__device__ float d_WhhgT[64*256];
__device__ float d_bm[512], d_bu[512], d_bg[256];
__device__ float d_xzm[1280*512];
__device__ float d_xzu[320*512];
__device__ float d_xzg[64*256];
__device__ float d_aggr[320*128];
__device__ float d_aggn[64*128];
__device__ float d_upd[320*128];
__device__ float d_grp[64*64];
__device__ int   d_e2g[1280];
__device__ int   d_off[64];

__device__ __forceinline__ float sigf(float x) { return 1.0f / (1.0f + expf(-x)); }

// ---------------- prep: e2g map, offsets, fused biases, +inf init ----------------
__global__ void k_prep(const int* __restrict__ num_edges, const int* __restrict__ bidx,
                       const float* __restrict__ bihm, const float* __restrict__ bhhm,
                       const float* __restrict__ bihu, const float* __restrict__ bhhu,
                       const float* __restrict__ bihg, const float* __restrict__ bhhg)
{
    __shared__ int ce[65];
    int tid = threadIdx.x;
    if (tid == 0) {
        ce[0] = 0;
        for (int g = 0; g < 64; g++) ce[g + 1] = ce[g] + num_edges[g];
        int cnt[64];
        for (int g = 0; g < 64; g++) cnt[g] = 0;
        for (int i = 0; i < 320; i++) cnt[bidx[i]]++;
        int acc = 0;
        for (int g = 0; g < 64; g++) { d_off[g] = acc; acc += cnt[g]; }
    }
    __syncthreads();
    for (int e = tid; e < 1280; e += blockDim.x) {
        int g = 0;
        while (g < 63 && e >= ce[g + 1]) g++;
        d_e2g[e] = g;
    }
    for (int i = tid; i < 512; i += blockDim.x) { d_bm[i] = bihm[i] + bhhm[i]; d_bu[i] = bihu[i] + bhhu[i]; }
    for (int i = tid; i < 256; i += blockDim.x) d_bg[i] = bihg[i] + bhhg[i];
    const float INF = __int_as_float(0x7f800000);
    for (int i = tid; i < 320 * 128; i += blockDim.x) d_aggr[i] = INF;
    for (int i = tid; i < 64 * 128; i += blockDim.x) d_aggn[i] = INF;
}

// ---------------- transpose all weight matrices to k-major ----------------
__global__ void k_transpose_all(const float* __restrict__ Wihm, const float* __restrict__ Whhm,
                                const float* __restrict__ Wihu, const float* __restrict__ Whhu,
                                const float* __restrict__ Wihg, const float* __restrict__ Whhg)
{
    int tid = blockIdx.x * blockDim.x + threadIdx.x;
    int stride = gridDim.x * blockDim.x;
    for (int i = tid; i < 144 * 512; i += stride) { int k = i >> 9, j = i & 511; d_WihmT[i] = Wihm[j * 144 + k]; }
    for (int i = tid; i < 128 * 512; i += stride) { int k = i >> 9, j = i & 511; d_WhhmT[i] = Whhm[j * 128 + k]; }
    for (int i = tid; i < 208 * 512; i += stride) { int k = i >> 9, j = i & 511; d_WihuT[i] = Wihu[j * 208 + k]; }
    for (int i = tid; i < 128 * 512; i += stride) { int k = i >> 9, j = i & 511; d_WhhuT[i] = Whhu[j * 128 + k]; }
    for (int i = tid; i < 144 * 256; i += stride) { int k = i >> 8, j = i & 255; d_WihgT[i] = Wihg[j * 144 + k]; }
    for (int i = tid; i <  64 * 256; i += stride) { int k = i >> 8, j = i & 255; d_WhhgT[i] = Whhg[j * 64 + k]; }
}

// ---------------- input projections (t = 255 slice only) ----------------
__global__ void __launch_bounds__(512) k_xzm(const float* __restrict__ nodes,
                                             const float* __restrict__ ga,
                                             const int* __restrict__ eidx)
{
    __shared__ float feat[144];
    int e = blockIdx.x, j = threadIdx.x;
    if (j < 64) {
        int src = eidx[e];                                  // faithful: src == tgt
        float v = nodes[(src * 256 + 255) * 64 + j];
        feat[j] = v; feat[64 + j] = v;
    } else if (j < 80) {
        int g = d_e2g[e];
        feat[128 + (j - 64)] = ga[(g * 256 + 255) * 16 + (j - 64)];
    }
    __syncthreads();
    float a0 = d_bm[j], a1 = 0.f, a2 = 0.f, a3 = 0.f;
    #pragma unroll 4
    for (int k = 0; k < 144; k += 4) {
        a0 += d_WihmT[(k    ) * 512 + j] * feat[k    ];
        a1 += d_WihmT[(k + 1) * 512 + j] * feat[k + 1];
        a2 += d_WihmT[(k + 2) * 512 + j] * feat[k + 2];
        a3 += d_WihmT[(k + 3) * 512 + j] * feat[k + 3];
    }
    d_xzm[e * 512 + j] = (a0 + a1) + (a2 + a3);
}

__global__ void __launch_bounds__(512) k_xzu(const float* __restrict__ nodes,
                                             const float* __restrict__ ga,
                                             const int* __restrict__ bidx)
{
    __shared__ float feat[208];
    int n = blockIdx.x, j = threadIdx.x;
    if (j < 64)        feat[j] = nodes[(n * 256 + 255) * 64 + j];
    else if (j < 192)  feat[j] = d_aggr[n * 128 + (j - 64)];
    else if (j < 208)  { int g = bidx[n]; feat[j] = ga[(g * 256 + 255) * 16 + (j - 192)]; }
    __syncthreads();
    float a0 = d_bu[j], a1 = 0.f, a2 = 0.f, a3 = 0.f;
    #pragma unroll 4
    for (int k = 0; k < 208; k += 4) {
        a0 += d_WihuT[(k    ) * 512 + j] * feat[k    ];
        a1 += d_WihuT[(k + 1) * 512 + j] * feat[k + 1];
        a2 += d_WihuT[(k + 2) * 512 + j] * feat[k + 2];
        a3 += d_WihuT[(k + 3) * 512 + j] * feat[k + 3];
    }
    d_xzu[n * 512 + j] = (a0 + a1) + (a2 + a3);
}

__global__ void __launch_bounds__(256) k_xzg(const float* __restrict__ ga)
{
    __shared__ float feat[144];
    int g = blockIdx.x, j = threadIdx.x;
    if (j < 128)       feat[j] = d_aggn[g * 128 + j];
    else if (j < 144)  feat[j] = ga[(g * 256 + 255) * 16 + (j - 128)];
    __syncthreads();
    float a0 = d_bg[j], a1 = 0.f, a2 = 0.f, a3 = 0.f;
    #pragma unroll 4
    for (int k = 0; k < 144; k += 4) {
        a0 += d_WihgT[(k    ) * 256 + j] * feat[k    ];
        a1 += d_WihgT[(k + 1) * 256 + j] * feat[k + 1];
        a2 += d_WihgT[(k + 2) * 256 + j] * feat[k + 2];
        a3 += d_WihgT[(k + 3) * 256 + j] * feat[k + 3];
    }
    d_xzg[g * 256 + j] = (a0 + a1) + (a2 + a3);
}

// ---------------- sequential LSTM core (single CTA, 4H threads) ----------------
template <int H>
__device__ __forceinline__ void lstm_body(const float* __restrict__ xz,
                                          const float* __restrict__ WT, int steps,
                                          const int* __restrict__ idxArr,
                                          float* __restrict__ minBuf,
                                          float* __restrict__ storeBuf)
{
    constexpr int J = 4 * H;
    __shared__ float h_s[H], c_s[H], z_s[J];
    int j = threadIdx.x;
    if (j < H) { h_s[j] = 0.f; c_s[j] = 0.f; }
    __syncthreads();
    for (int s = 0; s < steps; s++) {
        float a0 = xz[s * J + j], a1 = 0.f, a2 = 0.f, a3 = 0.f;
        #pragma unroll 8
        for (int k = 0; k < H; k += 4) {
            a0 += WT[(k    ) * J + j] * h_s[k    ];
            a1 += WT[(k + 1) * J + j] * h_s[k + 1];
            a2 += WT[(k + 2) * J + j] * h_s[k + 2];
            a3 += WT[(k + 3) * J + j] * h_s[k + 3];
        }
        z_s[j] = (a0 + a1) + (a2 + a3);
        __syncthreads();
        if (j < H) {
            float zi = z_s[j], zf = z_s[H + j], zg = z_s[2 * H + j], zo = z_s[3 * H + j];
            float cc = sigf(zf) * c_s[j] + sigf(zi) * tanhf(zg);
            float hh = sigf(zo) * tanhf(cc);
            c_s[j] = cc; h_s[j] = hh;
            float m = fmaxf(hh, 0.f);                       // relu on outputs only
            if (storeBuf) storeBuf[s * H + j] = m;
            if (minBuf) { int t = idxArr[s]; minBuf[t * H + j] = fminf(minBuf[t * H + j], m); }
        }
        __syncthreads();
    }
}

__global__ void __launch_bounds__(512) k_lstm_msg(const int* __restrict__ src)
{ lstm_body<128>(d_xzm, d_WhhmT, 1280, src, d_aggr, nullptr); }

__global__ void __launch_bounds__(512) k_lstm_upd(const int* __restrict__ bidx)
{ lstm_body<128>(d_xzu, d_WhhuT, 320, bidx, d_aggn, d_upd); }

__global__ void __launch_bounds__(256) k_lstm_grp()
{ lstm_body<64>(d_xzg, d_WhhgT, 64, nullptr, nullptr, d_grp); }

// ---------------- tail: chosen gather + action LSTM + softmax ----------------
__global__ void __launch_bounds__(64) k_tail(const int* __restrict__ cw,
                                             const float* __restrict__ Wiha,
                                             const float* __restrict__ Whha,
                                             const float* __restrict__ biha,
                                             const float* __restrict__ bhha,
                                             float* __restrict__ out)
{
    __shared__ float xza[64 * 16], res[64 * 4], zb[16], hb[4], cb[4];
    int tid = threadIdx.x;
    {   // per-graph action-LSTM input projection
        int g = tid;
        int c = cw[g];
        int adj = (c == 3) ? 2 : c;
        int atbw = (g == 0) ? c : (adj + d_off[g]);         // faithful: g==0 not offset
        const float* ch = (c == 3) ? &d_aggn[g * 128] : &d_upd[atbw * 128];
        for (int j = 0; j < 16; j++) {
            float a = biha[j] + bhha[j];
            const float* w = &Wiha[j * 192];
            for (int k = 0; k < 128; k++) a += w[k] * ch[k];
            for (int k = 0; k < 64;  k++) a += w[128 + k] * d_grp[g * 64 + k];
            xza[g * 16 + j] = a;
        }
    }
    if (tid < 4) { hb[tid] = 0.f; cb[tid] = 0.f; }
    __syncthreads();
    if (tid < 32) {                                          // 64-step action recurrence
        for (int s = 0; s < 64; s++) {
            if (tid < 16) {
                float z = xza[s * 16 + tid];
                #pragma unroll
                for (int k = 0; k < 4; k++) z += Whha[tid * 4 + k] * hb[k];
                zb[tid] = z;
            }
            __syncwarp();
            if (tid < 4) {
                float zi = zb[tid], zf = zb[4 + tid], zg = zb[8 + tid], zo = zb[12 + tid];
                float cc = sigf(zf) * cb[tid] + sigf(zi) * tanhf(zg);
                float hh = sigf(zo) * tanhf(cc);
                cb[tid] = cc; hb[tid] = hh;
                res[s * 4 + tid] = hh;                      // ys[s] at batch col t=255
            }
            __syncwarp();
        }
    }
    __syncthreads();
    {   // softmax per graph
        int g = tid;
        float r0 = res[g * 4], r1 = res[g * 4 + 1], r2 = res[g * 4 + 2], r3 = res[g * 4 + 3];
        float mx = fmaxf(fmaxf(r0, r1), fmaxf(r2, r3));
        float e0 = expf(r0 - mx), e1 = expf(r1 - mx), e2 = expf(r2 - mx), e3 = expf(r3 - mx);
        float inv = 1.f / (e0 + e1 + e2 + e3);
        out[g * 4] = e0 * inv; out[g * 4 + 1] = e1 * inv;
        out[g * 4 + 2] = e2 * inv; out[g * 4 + 3] = e3 * inv;
    }
}

extern "C" void kernel_launch(void* const* d_in, const int* in_sizes, int n_in,
                              void* d_out, int out_size)
{
    const float* nodes = (const float*)d_in[0];
    const float* ga    = (const float*)d_in[1];
    const int*   eidx  = (const int*)d_in[2];
    const int*   num_edges = (const int*)d_in[4];
    const int*   bidx  = (const int*)d_in[5];
    const int*   cw    = (const int*)d_in[6];
    const float* Wihm = (const float*)d_in[7],  *Whhm = (const float*)d_in[8];
    const float* bihm = (const float*)d_in[9],  *bhhm = (const float*)d_in[10];
    const float* Wihu = (const float*)d_in[11], *Whhu = (const float*)d_in[12];
    const float* bihu = (const float*)d_in[13], *bhhu = (const float*)d_in[14];
    const float* Wihg = (const float*)d_in[15], *Whhg = (const float*)d_in[16];
    const float* bihg = (const float*)d_in[17], *bhhg = (const float*)d_in[18];
    const float* Wiha = (const float*)d_in[19], *Whha = (const float*)d_in[20];
    const float* biha = (const float*)d_in[21], *bhha = (const float*)d_in[22];
    float* out = (float*)d_out;

    k_prep<<<1, 256>>>(num_edges, bidx, bihm, bhhm, bihu, bhhu, bihg, bhhg);
    k_transpose_all<<<360, 256>>>(Wihm, Whhm, Wihu, Whhu, Wihg, Whhg);
    k_xzm<<<1280, 512>>>(nodes, ga, eidx);
    k_lstm_msg<<<1, 512>>>(eidx);                 // idx = edge_indices[0] (src==tgt)
    k_xzu<<<320, 512>>>(nodes, ga, bidx);
    k_lstm_upd<<<1, 512>>>(bidx);
    k_xzg<<<64, 256>>>(ga);
    k_lstm_grp<<<1, 256>>>();
    k_tail<<<1, 64>>>(cw, Wiha, Whha, biha, bhha, out);
}

// round 9
// speedup vs baseline: 2.2910x; 2.2910x over previous
#include <cuda_runtime.h>
#include <math.h>

// Shapes (fixed by setup_inputs)
// nodes [320,256,64], global_attr [64*256,16], edges [2,1280], out [64,4] f32
// LSTMs: msg 4H=512,H=128,Din=144 ; upd 512/128/208 ; grp 256/64/144 ; act 16/4/192

__device__ float d_WihmT[144*512];
__device__ float d_WhhmT[128*512];
__device__ float d_WihuT[208*512];
__device__ float d_WhhuT[128*512];
__device__ float d_WihgT[144*256];
__device__ float d_bm[512], d_bu[512], d_bg[256];
__device__ float d_xzm[1280*512];
__device__ float d_xzu[320*512];
__device__ float d_xzg[64*256];
__device__ float d_aggr[320*128];
__device__ float d_aggn[64*128];
__device__ float d_upd[320*128];
__device__ float d_grp[64*64];
__device__ int   d_e2g[1280];
__device__ int   d_off[64];

__device__ __forceinline__ float sigf(float x) { return 1.0f / (1.0f + expf(-x)); }

// ---------------- prep: e2g map, offsets, fused biases, +inf init ----------------
__global__ void k_prep(const int* __restrict__ num_edges, const int* __restrict__ bidx,
                       const float* __restrict__ bihm, const float* __restrict__ bhhm,
                       const float* __restrict__ bihu, const float* __restrict__ bhhu,
                       const float* __restrict__ bihg, const float* __restrict__ bhhg)
{
    __shared__ int ce[65];
    int tid = threadIdx.x;
    if (tid == 0) {
        ce[0] = 0;
        for (int g = 0; g < 64; g++) ce[g + 1] = ce[g] + num_edges[g];
        int cnt[64];
        for (int g = 0; g < 64; g++) cnt[g] = 0;
        for (int i = 0; i < 320; i++) cnt[bidx[i]]++;
        int acc = 0;
        for (int g = 0; g < 64; g++) { d_off[g] = acc; acc += cnt[g]; }
    }
    __syncthreads();
    for (int e = tid; e < 1280; e += blockDim.x) {
        int g = 0;
        while (g < 63 && e >= ce[g + 1]) g++;
        d_e2g[e] = g;
    }
    for (int i = tid; i < 512; i += blockDim.x) { d_bm[i] = bihm[i] + bhhm[i]; d_bu[i] = bihu[i] + bhhu[i]; }
    for (int i = tid; i < 256; i += blockDim.x) d_bg[i] = bihg[i] + bhhg[i];
    const float INF = __int_as_float(0x7f800000);
    for (int i = tid; i < 320 * 128; i += blockDim.x) d_aggr[i] = INF;
    for (int i = tid; i < 64 * 128; i += blockDim.x) d_aggn[i] = INF;
}

// ---------------- transpose weight matrices to k-major ----------------
__global__ void k_transpose_all(const float* __restrict__ Wihm, const float* __restrict__ Whhm,
                                const float* __restrict__ Wihu, const float* __restrict__ Whhu,
                                const float* __restrict__ Wihg)
{
    int tid = blockIdx.x * blockDim.x + threadIdx.x;
    int stride = gridDim.x * blockDim.x;
    for (int i = tid; i < 144 * 512; i += stride) { int k = i >> 9, j = i & 511; d_WihmT[i] = Wihm[j * 144 + k]; }
    for (int i = tid; i < 128 * 512; i += stride) { int k = i >> 9, j = i & 511; d_WhhmT[i] = Whhm[j * 128 + k]; }
    for (int i = tid; i < 208 * 512; i += stride) { int k = i >> 9, j = i & 511; d_WihuT[i] = Wihu[j * 208 + k]; }
    for (int i = tid; i < 128 * 512; i += stride) { int k = i >> 9, j = i & 511; d_WhhuT[i] = Whhu[j * 128 + k]; }
    for (int i = tid; i < 144 * 256; i += stride) { int k = i >> 8, j = i & 255; d_WihgT[i] = Wihg[j * 144 + k]; }
}

// ---------------- input projections (t = 255 slice only) ----------------
__global__ void __launch_bounds__(512) k_xzm(const float* __restrict__ nodes,
                                             const float* __restrict__ ga,
                                             const int* __restrict__ eidx)
{
    __shared__ float feat[144];
    int e = blockIdx.x, j = threadIdx.x;
    if (j < 64) {
        int src = eidx[e];                                  // faithful: src == tgt
        float v = nodes[(src * 256 + 255) * 64 + j];
        feat[j] = v; feat[64 + j] = v;
    } else if (j < 80) {
        int g = d_e2g[e];
        feat[128 + (j - 64)] = ga[(g * 256 + 255) * 16 + (j - 64)];
    }
    __syncthreads();
    float a0 = d_bm[j], a1 = 0.f, a2 = 0.f, a3 = 0.f;
    #pragma unroll 4
    for (int k = 0; k < 144; k += 4) {
        a0 += d_WihmT[(k    ) * 512 + j] * feat[k    ];
        a1 += d_WihmT[(k + 1) * 512 + j] * feat[k + 1];
        a2 += d_WihmT[(k + 2) * 512 + j] * feat[k + 2];
        a3 += d_WihmT[(k + 3) * 512 + j] * feat[k + 3];
    }
    d_xzm[e * 512 + j] = (a0 + a1) + (a2 + a3);
}

__global__ void __launch_bounds__(512) k_xzu(const float* __restrict__ nodes,
                                             const float* __restrict__ ga,
                                             const int* __restrict__ bidx)
{
    __shared__ float feat[208];
    int n = blockIdx.x, j = threadIdx.x;
    if (j < 64)        feat[j] = nodes[(n * 256 + 255) * 64 + j];
    else if (j < 192)  feat[j] = d_aggr[n * 128 + (j - 64)];
    else if (j < 208)  { int g = bidx[n]; feat[j] = ga[(g * 256 + 255) * 16 + (j - 192)]; }
    __syncthreads();
    float a0 = d_bu[j], a1 = 0.f, a2 = 0.f, a3 = 0.f;
    #pragma unroll 4
    for (int k = 0; k < 208; k += 4) {
        a0 += d_WihuT[(k    ) * 512 + j] * feat[k    ];
        a1 += d_WihuT[(k + 1) * 512 + j] * feat[k + 1];
        a2 += d_WihuT[(k + 2) * 512 + j] * feat[k + 2];
        a3 += d_WihuT[(k + 3) * 512 + j] * feat[k + 3];
    }
    d_xzu[n * 512 + j] = (a0 + a1) + (a2 + a3);
}

__global__ void __launch_bounds__(256) k_xzg(const float* __restrict__ ga)
{
    __shared__ float feat[144];
    int g = blockIdx.x, j = threadIdx.x;
    if (j < 128)       feat[j] = d_aggn[g * 128 + j];
    else if (j < 144)  feat[j] = ga[(g * 256 + 255) * 16 + (j - 128)];
    __syncthreads();
    float a0 = d_bg[j], a1 = 0.f, a2 = 0.f, a3 = 0.f;
    #pragma unroll 4
    for (int k = 0; k < 144; k += 4) {
        a0 += d_WihgT[(k    ) * 256 + j] * feat[k    ];
        a1 += d_WihgT[(k + 1) * 256 + j] * feat[k + 1];
        a2 += d_WihgT[(k + 2) * 256 + j] * feat[k + 2];
        a3 += d_WihgT[(k + 3) * 256 + j] * feat[k + 3];
    }
    d_xzg[g * 256 + j] = (a0 + a1) + (a2 + a3);
}

// ---------------- sequential LSTM core: Whh cached in smem + registers ----------------
// Whh rows [0, SMROWS) live in smem (per-j contiguous, stride SMROWS+4 -> conflict-free
// LDS.128); rows [SMROWS, H) live in registers (RR fp32 per thread, loaded once from
// the k-major transpose WT, coalesced). Per step only h (broadcast LDS) and the smem
// half cross the crossbar.
template <int H, int SMROWS>
__device__ __forceinline__ void lstm_cached(const float* __restrict__ xz,
                                            const float* __restrict__ WT,    // k-major [H][4H]
                                            const float* __restrict__ Whh,   // original [4H][H]
                                            int steps, const int* __restrict__ idxArr,
                                            float* __restrict__ minBuf,
                                            float* __restrict__ storeBuf)
{
    constexpr int J   = 4 * H;
    constexpr int RR  = H - SMROWS;
    constexpr int STR = SMROWS + 4;          // 4j bank offset per thread -> conflict-free
    extern __shared__ float smem[];
    float* Wsm = smem;                        // [J][STR]
    float* h_s = smem + J * STR;              // [H] (16B aligned: J*STR*4 is mult of 16)
    float* c_s = h_s + H;
    float* z_s = c_s + H;
    int j = threadIdx.x;

    for (int idx = j; idx < J * SMROWS; idx += J) {
        int jj = idx / SMROWS, kk = idx - jj * SMROWS;
        Wsm[jj * STR + kk] = Whh[jj * H + kk];
    }
    float wr[RR > 0 ? RR : 1];
    if (RR > 0) {
        #pragma unroll
        for (int i = 0; i < RR; i++) wr[i] = WT[(SMROWS + i) * J + j];
    }
    if (j < H) { h_s[j] = 0.f; c_s[j] = 0.f; }
    __syncthreads();

    const float4* h4 = reinterpret_cast<const float4*>(h_s);
    const float4* w4 = reinterpret_cast<const float4*>(&Wsm[j * STR]);
    float xnext = xz[j];
    for (int s = 0; s < steps; s++) {
        float a0 = xnext, a1 = 0.f, a2 = 0.f, a3 = 0.f;
        if (s + 1 < steps) xnext = xz[(s + 1) * J + j];     // prefetch next step's xz
        #pragma unroll
        for (int k4 = 0; k4 < SMROWS / 4; k4++) {
            float4 hv = h4[k4];
            float4 wv = w4[k4];
            a0 += wv.x * hv.x; a1 += wv.y * hv.y; a2 += wv.z * hv.z; a3 += wv.w * hv.w;
        }
        #pragma unroll
        for (int k4 = 0; k4 < RR / 4; k4++) {
            float4 hv = h4[SMROWS / 4 + k4];
            a0 += wr[4 * k4 + 0] * hv.x; a1 += wr[4 * k4 + 1] * hv.y;
            a2 += wr[4 * k4 + 2] * hv.z; a3 += wr[4 * k4 + 3] * hv.w;
        }
        z_s[j] = (a0 + a1) + (a2 + a3);
        __syncthreads();
        if (j < H) {
            float zi = z_s[j], zf = z_s[H + j], zg = z_s[2 * H + j], zo = z_s[3 * H + j];
            float cc = sigf(zf) * c_s[j] + sigf(zi) * tanhf(zg);
            float hh = sigf(zo) * tanhf(cc);
            c_s[j] = cc; h_s[j] = hh;
            float m = fmaxf(hh, 0.f);                       // relu on outputs only
            if (storeBuf) storeBuf[s * H + j] = m;
            if (minBuf) { int t = idxArr[s]; float* p = &minBuf[t * H + j]; *p = fminf(*p, m); }
        }
        __syncthreads();
    }
}

__global__ void __launch_bounds__(512) k_lstm_msg(const int* __restrict__ src,
                                                  const float* __restrict__ Whhm)
{ lstm_cached<128, 64>(d_xzm, d_WhhmT, Whhm, 1280, src, d_aggr, nullptr); }

__global__ void __launch_bounds__(512) k_lstm_upd(const int* __restrict__ bidx,
                                                  const float* __restrict__ Whhu)
{ lstm_cached<128, 64>(d_xzu, d_WhhuT, Whhu, 320, bidx, d_aggn, d_upd); }

__global__ void __launch_bounds__(256) k_lstm_grp(const float* __restrict__ Whhg)
{ lstm_cached<64, 64>(d_xzg, nullptr, Whhg, 64, nullptr, nullptr, d_grp); }

// ---------------- tail: chosen gather + action LSTM + softmax ----------------
__global__ void __launch_bounds__(64) k_tail(const int* __restrict__ cw,
                                             const float* __restrict__ Wiha,
                                             const float* __restrict__ Whha,
                                             const float* __restrict__ biha,
                                             const float* __restrict__ bhha,
                                             float* __restrict__ out)
{
    __shared__ float xza[64 * 16], res[64 * 4], zb[16], hb[4], cb[4];
    int tid = threadIdx.x;
    {   // per-graph action-LSTM input projection
        int g = tid;
        int c = cw[g];
        int adj = (c == 3) ? 2 : c;
        int atbw = (g == 0) ? c : (adj + d_off[g]);         // faithful: g==0 not offset
        const float* ch = (c == 3) ? &d_aggn[g * 128] : &d_upd[atbw * 128];
        for (int j = 0; j < 16; j++) {
            float a = biha[j] + bhha[j];
            const float* w = &Wiha[j * 192];
            for (int k = 0; k < 128; k++) a += w[k] * ch[k];
            for (int k = 0; k < 64;  k++) a += w[128 + k] * d_grp[g * 64 + k];
            xza[g * 16 + j] = a;
        }
    }
    if (tid < 4) { hb[tid] = 0.f; cb[tid] = 0.f; }
    __syncthreads();
    if (tid < 32) {                                          // 64-step action recurrence
        for (int s = 0; s < 64; s++) {
            if (tid < 16) {
                float z = xza[s * 16 + tid];
                #pragma unroll
                for (int k = 0; k < 4; k++) z += Whha[tid * 4 + k] * hb[k];
                zb[tid] = z;
            }
            __syncwarp();
            if (tid < 4) {
                float zi = zb[tid], zf = zb[4 + tid], zg = zb[8 + tid], zo = zb[12 + tid];
                float cc = sigf(zf) * cb[tid] + sigf(zi) * tanhf(zg);
                float hh = sigf(zo) * tanhf(cc);
                cb[tid] = cc; hb[tid] = hh;
                res[s * 4 + tid] = hh;                      // ys[s] at batch col t=255
            }
            __syncwarp();
        }
    }
    __syncthreads();
    {   // softmax per graph
        int g = tid;
        float r0 = res[g * 4], r1 = res[g * 4 + 1], r2 = res[g * 4 + 2], r3 = res[g * 4 + 3];
        float mx = fmaxf(fmaxf(r0, r1), fmaxf(r2, r3));
        float e0 = expf(r0 - mx), e1 = expf(r1 - mx), e2 = expf(r2 - mx), e3 = expf(r3 - mx);
        float inv = 1.f / (e0 + e1 + e2 + e3);
        out[g * 4] = e0 * inv; out[g * 4 + 1] = e1 * inv;
        out[g * 4 + 2] = e2 * inv; out[g * 4 + 3] = e3 * inv;
    }
}

extern "C" void kernel_launch(void* const* d_in, const int* in_sizes, int n_in,
                              void* d_out, int out_size)
{
    const float* nodes = (const float*)d_in[0];
    const float* ga    = (const float*)d_in[1];
    const int*   eidx  = (const int*)d_in[2];
    const int*   num_edges = (const int*)d_in[4];
    const int*   bidx  = (const int*)d_in[5];
    const int*   cw    = (const int*)d_in[6];
    const float* Wihm = (const float*)d_in[7],  *Whhm = (const float*)d_in[8];
    const float* bihm = (const float*)d_in[9],  *bhhm = (const float*)d_in[10];
    const float* Wihu = (const float*)d_in[11], *Whhu = (const float*)d_in[12];
    const float* bihu = (const float*)d_in[13], *bhhu = (const float*)d_in[14];
    const float* Wihg = (const float*)d_in[15], *Whhg = (const float*)d_in[16];
    const float* bihg = (const float*)d_in[17], *bhhg = (const float*)d_in[18];
    const float* Wiha = (const float*)d_in[19], *Whha = (const float*)d_in[20];
    const float* biha = (const float*)d_in[21], *bhha = (const float*)d_in[22];
    float* out = (float*)d_out;

    const int SMEM_BIG = (512 * 68 + 128 + 128 + 512) * 4;   // 142336 B
    const int SMEM_GRP = (256 * 68 + 64 + 64 + 256) * 4;     //  71168 B
    cudaFuncSetAttribute(k_lstm_msg, cudaFuncAttributeMaxDynamicSharedMemorySize, SMEM_BIG);
    cudaFuncSetAttribute(k_lstm_upd, cudaFuncAttributeMaxDynamicSharedMemorySize, SMEM_BIG);
    cudaFuncSetAttribute(k_lstm_grp, cudaFuncAttributeMaxDynamicSharedMemorySize, SMEM_GRP);

    k_prep<<<1, 256>>>(num_edges, bidx, bihm, bhhm, bihu, bhhu, bihg, bhhg);
    k_transpose_all<<<360, 256>>>(Wihm, Whhm, Wihu, Whhu, Wihg);
    k_xzm<<<1280, 512>>>(nodes, ga, eidx);
    k_lstm_msg<<<1, 512, SMEM_BIG>>>(eidx, Whhm);           // idx = edge_indices[0]
    k_xzu<<<320, 512>>>(nodes, ga, bidx);
    k_lstm_upd<<<1, 512, SMEM_BIG>>>(bidx, Whhu);
    k_xzg<<<64, 256>>>(ga);
    k_lstm_grp<<<1, 256, SMEM_GRP>>>(Whhg);
    k_tail<<<1, 64>>>(cw, Wiha, Whha, biha, bhha, out);
}